// round 3
// baseline (speedup 1.0000x reference)
#include <cuda_runtime.h>

typedef unsigned long long u64;

#define DN 50000
#define DE 800000
#define DK 40000
#define NBLK 49   // ceil(DN/1024)

// ---------------- scratch layout (single __device__ blob, no allocations) ----
static constexpr size_t OFF_H1   = 0;
static constexpr size_t OFF_AGG  = OFF_H1  + (size_t)DN*128*4;
static constexpr size_t OFF_HP   = OFF_AGG + (size_t)DN*128*4;
static constexpr size_t OFF_GM   = OFF_HP  + (size_t)DK*128*4;
static constexpr size_t OFF_DIS1 = OFF_GM  + (size_t)DK*128*4;
static constexpr size_t OFF_DIS2 = OFF_DIS1 + (size_t)DN*4;
static constexpr size_t OFF_DEG  = OFF_DIS2 + (size_t)DK*4;
static constexpr size_t OFF_SCORE= OFF_DEG  + (size_t)DN*4;
static constexpr size_t OFF_KEY  = OFF_SCORE+ (size_t)DN*4;
static constexpr size_t OFF_NEW  = OFF_KEY  + (size_t)DN*8;
static constexpr size_t OFF_NS   = OFF_NEW  + (size_t)DN*4;
static constexpr size_t OFF_ND   = OFF_NS   + (size_t)DE*4;
static constexpr size_t OFF_BINS = OFF_ND   + (size_t)DE*4;
static constexpr size_t OFF_BSUM = OFF_BINS + 256*4;
static constexpr size_t OFF_BOFF = OFF_BSUM + 64*4;
static constexpr size_t OFF_PFX  = OFF_BOFF + 64*4;
static constexpr size_t OFF_REM  = OFF_PFX  + 8;
static constexpr size_t OFF_WN   = OFF_REM  + 4;
static constexpr size_t OFF_ACC  = OFF_WN   + 4;
static constexpr size_t TOTAL_BYTES = OFF_ACC + 64*4;

__device__ __align__(256) unsigned char g_scratch[TOTAL_BYTES];

// ---------------- small utility kernels ----------------
__global__ void init_kernel(int* deg, int* bins, float* acc, int* rem, u64* pfx){
    int i = blockIdx.x*blockDim.x + threadIdx.x;
    if (i < DN)  deg[i]  = 0;
    if (i < 256) bins[i] = 0;
    if (i < 64)  acc[i]  = 0.f;
    if (i == 0){ *rem = DK; *pfx = 0ull; }
}

__global__ void zero4_kernel(float4* p, int n){
    int i = blockIdx.x*blockDim.x + threadIdx.x;
    if (i < n) p[i] = make_float4(0.f,0.f,0.f,0.f);
}

__global__ void zeroi_kernel(int* p, int n){
    int i = blockIdx.x*blockDim.x + threadIdx.x;
    if (i < n) p[i] = 0;
}

// ---------------- GEMM: Y[M,KOUT] = X[M,KIN] @ W[KIN,KOUT] ----------------
template<int KIN, int KOUT, int ROWS>
__global__ void gemm_kernel(const float* __restrict__ X, const float* __restrict__ W,
                            float* __restrict__ Y, int M){
    __shared__ __align__(16) float sW[KIN*KOUT];
    __shared__ __align__(16) float sX[ROWS*KIN];
    const int tid = threadIdx.x;
    for (int i = tid; i < KIN*KOUT/4; i += blockDim.x)
        ((float4*)sW)[i] = ((const float4*)W)[i];
    const int row0 = blockIdx.x * ROWS;
    for (int i = tid; i < ROWS*KIN/4; i += blockDim.x){
        int r  = i / (KIN/4);
        int gr = row0 + r;
        ((float4*)sX)[i] = (gr < M) ? ((const float4*)X)[(size_t)gr*(KIN/4) + (i % (KIN/4))]
                                    : make_float4(0.f,0.f,0.f,0.f);
    }
    __syncthreads();
    for (int idx = tid; idx < ROWS*(KOUT/4); idx += blockDim.x){
        int r  = idx / (KOUT/4);
        int c4 = idx % (KOUT/4);
        const float* xr = sX + r*KIN;
        float4 acc = make_float4(0.f,0.f,0.f,0.f);
        #pragma unroll 16
        for (int k = 0; k < KIN; k++){
            float  xv = xr[k];
            float4 w  = ((const float4*)sW)[k*(KOUT/4) + c4];
            acc.x += xv*w.x; acc.y += xv*w.y; acc.z += xv*w.z; acc.w += xv*w.w;
        }
        int gr = row0 + r;
        if (gr < M) ((float4*)Y)[(size_t)gr*(KOUT/4) + c4] = acc;
    }
}

// ---------------- degree / normalization ----------------
__global__ void deg_kernel(const int* __restrict__ dst, int* __restrict__ deg){
    int e = blockIdx.x*blockDim.x + threadIdx.x;
    if (e < DE) atomicAdd(&deg[dst[e]], 1);
}

__global__ void dis_kernel(float* __restrict__ dis, const int* __restrict__ deg, int M){
    int n = blockIdx.x*blockDim.x + threadIdx.x;
    if (n < M) dis[n] = rsqrtf(1.0f + (float)deg[n]);
}

// ---------------- edge aggregation (vector red) ----------------
__device__ __forceinline__ void red_add_v4(float* p, float4 v){
    asm volatile("red.global.add.v4.f32 [%0], {%1,%2,%3,%4};"
                 :: "l"(p), "f"(v.x), "f"(v.y), "f"(v.z), "f"(v.w) : "memory");
}

template<int DIM, bool SKIP>
__global__ void edge_agg_kernel(const int* __restrict__ srcI, const int* __restrict__ dstI,
                                const float* __restrict__ dis,
                                const float* __restrict__ H, float* __restrict__ A){
    const int LPE = DIM/4;                // float4 lanes per edge
    int t = blockIdx.x*blockDim.x + threadIdx.x;
    int e   = t / LPE;
    int sub = t % LPE;
    if (e >= DE) return;
    int s = srcI[e];
    if (SKIP && s < 0) return;
    int d = dstI[e];
    float coef = dis[s] * dis[d];
    float4 v = ((const float4*)H)[(size_t)s*LPE + sub];
    v.x *= coef; v.y *= coef; v.z *= coef; v.w *= coef;
    red_add_v4(A + (size_t)d*DIM + sub*4, v);
}

// out = agg + h*dis^2 + b  (optional relu), written in-place into G
template<int DIM, bool RELU>
__global__ void finalize_kernel(float* __restrict__ G, const float* __restrict__ A,
                                const float* __restrict__ dis, const float* __restrict__ b, int M){
    int i = blockIdx.x*blockDim.x + threadIdx.x;
    if (i >= M*DIM) return;
    int n = i / DIM;
    int d = i - n*DIM;
    float ds = dis[n];
    float v = A[i] + G[i]*ds*ds + b[d];
    if (RELU) v = fmaxf(v, 0.f);
    G[i] = v;
}

// ---------------- pooling: score, exact top-K radix select ----------------
__global__ void wnorm_kernel(const float* __restrict__ w, float* wn){
    float v = w[threadIdx.x]; v *= v;
    #pragma unroll
    for (int o = 16; o; o >>= 1) v += __shfl_xor_sync(0xffffffffu, v, o);
    __shared__ float sh[4];
    if ((threadIdx.x & 31) == 0) sh[threadIdx.x >> 5] = v;
    __syncthreads();
    if (threadIdx.x == 0) *wn = sqrtf(sh[0]+sh[1]+sh[2]+sh[3]);
}

__global__ void score_kernel(const float* __restrict__ H, const float* __restrict__ w,
                             const float* __restrict__ wn,
                             float* __restrict__ score, u64* __restrict__ key){
    int t = blockIdx.x*blockDim.x + threadIdx.x;
    int n = t >> 5, lane = t & 31;
    if (n >= DN) return;
    float4 a = ((const float4*)H)[(size_t)n*32 + lane];
    float4 b = ((const float4*)w)[lane];
    float s = a.x*b.x + a.y*b.y + a.z*b.z + a.w*b.w;
    #pragma unroll
    for (int o = 16; o; o >>= 1) s += __shfl_xor_sync(0xffffffffu, s, o);
    if (lane == 0){
        s = tanhf(s / *wn);
        score[n] = s;
        unsigned ub = __float_as_uint(s);
        ub = (ub & 0x80000000u) ? ~ub : (ub | 0x80000000u);   // order-preserving map
        key[n] = ((u64)ub << 32) | (u64)(0xffffffffu - (unsigned)n);  // distinct keys
    }
}

__global__ void hist_kernel(const u64* __restrict__ key, int* __restrict__ bins,
                            const u64* __restrict__ pfxp, int shift){
    __shared__ int sb[256];
    if (threadIdx.x < 256) sb[threadIdx.x] = 0;
    __syncthreads();
    u64 pfx = *pfxp;
    for (int n = blockIdx.x*blockDim.x + threadIdx.x; n < DN; n += gridDim.x*blockDim.x){
        u64 k = key[n];
        bool ok = (shift == 56) || ((k >> (shift+8)) == (pfx >> (shift+8)));
        if (ok) atomicAdd(&sb[(int)((k >> shift) & 0xFF)], 1);
    }
    __syncthreads();
    if (threadIdx.x < 256 && sb[threadIdx.x]) atomicAdd(&bins[threadIdx.x], sb[threadIdx.x]);
}

__global__ void select_kernel(int* bins, u64* pfxp, int* remp, int shift){
    int rem = *remp;
    u64 pfx = *pfxp;
    for (int b = 255; b >= 0; b--){
        int c = bins[b];
        if (rem <= c){ pfx |= ((u64)b) << shift; break; }
        rem -= c;
    }
    *remp = rem;
    *pfxp = pfx;
    for (int i = 0; i < 256; i++) bins[i] = 0;
}

// ---------------- compaction: new_idx for kept nodes ----------------
__global__ void count_kept_kernel(const u64* __restrict__ key, const u64* __restrict__ pfxp,
                                  int* __restrict__ bsum){
    __shared__ int sh[256];
    u64 pfx = *pfxp;
    int tid = threadIdx.x;
    int base = blockIdx.x*1024 + tid*4;
    int c = 0;
    #pragma unroll
    for (int j = 0; j < 4; j++){
        int n = base + j;
        if (n < DN && key[n] >= pfx) c++;
    }
    sh[tid] = c;
    __syncthreads();
    for (int s = 128; s; s >>= 1){
        if (tid < s) sh[tid] += sh[tid + s];
        __syncthreads();
    }
    if (tid == 0) bsum[blockIdx.x] = sh[0];
}

__global__ void scan_kernel(const int* bsum, int* boff){
    int acc = 0;
    for (int i = 0; i < NBLK; i++){ boff[i] = acc; acc += bsum[i]; }
}

__global__ void newidx_kernel(const u64* __restrict__ key, const u64* __restrict__ pfxp,
                              const int* __restrict__ boff, int* __restrict__ newidx){
    __shared__ int sh[256];
    u64 pfx = *pfxp;
    int tid = threadIdx.x;
    int base = blockIdx.x*1024 + tid*4;
    int kept[4]; int cnt = 0;
    #pragma unroll
    for (int j = 0; j < 4; j++){
        int n = base + j;
        kept[j] = (n < DN && key[n] >= pfx) ? 1 : 0;
        cnt += kept[j];
    }
    sh[tid] = cnt;
    __syncthreads();
    for (int s = 1; s < 256; s <<= 1){
        int v = (tid >= s) ? sh[tid - s] : 0;
        __syncthreads();
        sh[tid] += v;
        __syncthreads();
    }
    int off = boff[blockIdx.x] + sh[tid] - cnt;   // exclusive prefix
    #pragma unroll
    for (int j = 0; j < 4; j++){
        int n = base + j;
        if (n < DN) newidx[n] = kept[j] ? off++ : -1;
    }
}

__global__ void build_hp_kernel(const float* __restrict__ H, const int* __restrict__ newidx,
                                const float* __restrict__ score, float* __restrict__ HP){
    int i = blockIdx.x*blockDim.x + threadIdx.x;
    if (i >= DN*32) return;
    int n = i >> 5;
    int ni = newidx[n];
    if (ni < 0) return;
    float s = score[n];
    float4 v = ((const float4*)H)[i];
    v.x *= s; v.y *= s; v.z *= s; v.w *= s;
    ((float4*)HP)[(size_t)ni*32 + (i & 31)] = v;
}

__global__ void remap_kernel(const int* __restrict__ src, const int* __restrict__ dst,
                             const int* __restrict__ newidx,
                             int* __restrict__ ns, int* __restrict__ nd, int* __restrict__ deg){
    int e = blockIdx.x*blockDim.x + threadIdx.x;
    if (e >= DE) return;
    int a = newidx[src[e]];
    int b = newidx[dst[e]];
    if (a >= 0 && b >= 0){
        ns[e] = a; nd[e] = b;
        atomicAdd(&deg[b], 1);
    } else { ns[e] = -1; nd[e] = -1; }
}

// conv4 finalize fused with global mean accumulation
__global__ void final_reduce_kernel(const float* __restrict__ G, const float* __restrict__ A,
                                    const float* __restrict__ dis, const float* __restrict__ b,
                                    float* __restrict__ acc){
    __shared__ float sh[64];
    if (threadIdx.x < 64) sh[threadIdx.x] = 0.f;
    __syncthreads();
    int stride = gridDim.x*blockDim.x;
    for (int i = blockIdx.x*blockDim.x + threadIdx.x; i < DK*64; i += stride){
        int n = i >> 6;
        int d = i & 63;
        float ds = dis[n];
        float v = A[i] + G[i]*ds*ds + b[d];
        atomicAdd(&sh[d], v);
    }
    __syncthreads();
    if (threadIdx.x < 64) atomicAdd(&acc[threadIdx.x], sh[threadIdx.x]);
}

__global__ void write_out_kernel(const float* __restrict__ acc, float* __restrict__ out){
    if (threadIdx.x < 64) out[threadIdx.x] = acc[threadIdx.x] * (1.0f/(float)DK);
}

// ---------------- launch ----------------
extern "C" void kernel_launch(void* const* d_in, const int* in_sizes, int n_in,
                              void* d_out, int out_size){
    const float* x   = (const float*)d_in[0];
    const int*   ei  = (const int*)  d_in[1];
    const int*   src = ei;
    const int*   dst = ei + DE;
    const float* W1  = (const float*)d_in[3];
    const float* b1  = (const float*)d_in[4];
    const float* pw  = (const float*)d_in[5];
    const float* W2  = (const float*)d_in[6];
    const float* b2  = (const float*)d_in[7];
    const float* W3  = (const float*)d_in[8];
    const float* b3  = (const float*)d_in[9];
    const float* W4  = (const float*)d_in[10];
    const float* b4  = (const float*)d_in[11];
    float* out = (float*)d_out;

    void* basep = nullptr;
    cudaGetSymbolAddress(&basep, g_scratch);
    unsigned char* B = (unsigned char*)basep;
    float* h1    = (float*)(B + OFF_H1);
    float* agg   = (float*)(B + OFF_AGG);
    float* hp    = (float*)(B + OFF_HP);
    float* gm    = (float*)(B + OFF_GM);
    float* dis1  = (float*)(B + OFF_DIS1);
    float* dis2  = (float*)(B + OFF_DIS2);
    int*   deg   = (int*)  (B + OFF_DEG);
    float* score = (float*)(B + OFF_SCORE);
    u64*   key   = (u64*)  (B + OFF_KEY);
    int*   nidx  = (int*)  (B + OFF_NEW);
    int*   ns    = (int*)  (B + OFF_NS);
    int*   nd    = (int*)  (B + OFF_ND);
    int*   bins  = (int*)  (B + OFF_BINS);
    int*   bsum  = (int*)  (B + OFF_BSUM);
    int*   boff  = (int*)  (B + OFF_BOFF);
    u64*   pfx   = (u64*)  (B + OFF_PFX);
    int*   rem   = (int*)  (B + OFF_REM);
    float* wn    = (float*)(B + OFF_WN);
    float* acc   = (float*)(B + OFF_ACC);

    const int T = 256;

    // init counters / accumulators (graph replays must fully reset state)
    init_kernel<<<(DN+T-1)/T, T>>>(deg, bins, acc, rem, pfx);

    // ---- conv1 on full graph ----
    gemm_kernel<64,128,16><<<(DN+15)/16, T>>>(x, W1, h1, DN);
    deg_kernel<<<(DE+T-1)/T, T>>>(dst, deg);
    dis_kernel<<<(DN+T-1)/T, T>>>(dis1, deg, DN);
    zero4_kernel<<<(DN*32+T-1)/T, T>>>((float4*)agg, DN*32);
    edge_agg_kernel<128,false><<<(DE*32+T-1)/T, T>>>(src, dst, dis1, h1, agg);
    finalize_kernel<128,true><<<(DN*128+T-1)/T, T>>>(h1, agg, dis1, b1, DN);

    // ---- TopK pooling ----
    wnorm_kernel<<<1,128>>>(pw, wn);
    score_kernel<<<(DN*32+T-1)/T, T>>>(h1, pw, wn, score, key);
    for (int shift = 56; shift >= 0; shift -= 8){
        hist_kernel<<<128, T>>>(key, bins, pfx, shift);
        select_kernel<<<1,1>>>(bins, pfx, rem, shift);
    }
    count_kept_kernel<<<NBLK, T>>>(key, pfx, bsum);
    scan_kernel<<<1,1>>>(bsum, boff);
    newidx_kernel<<<NBLK, T>>>(key, pfx, boff, nidx);
    build_hp_kernel<<<(DN*32+T-1)/T, T>>>(h1, nidx, score, hp);
    zeroi_kernel<<<(DK+T-1)/T, T>>>(deg, DK);
    remap_kernel<<<(DE+T-1)/T, T>>>(src, dst, nidx, ns, nd, deg);
    dis_kernel<<<(DK+T-1)/T, T>>>(dis2, deg, DK);

    // ---- conv2 (128 -> 64) + relu ----
    gemm_kernel<128,64,16><<<(DK+15)/16, T>>>(hp, W2, gm, DK);
    zero4_kernel<<<(DK*16+T-1)/T, T>>>((float4*)agg, DK*16);
    edge_agg_kernel<64,true><<<(DE*16+T-1)/T, T>>>(ns, nd, dis2, gm, agg);
    finalize_kernel<64,true><<<(DK*64+T-1)/T, T>>>(gm, agg, dis2, b2, DK);

    // ---- conv3 (64 -> 128) + relu ----
    gemm_kernel<64,128,16><<<(DK+15)/16, T>>>(gm, W3, hp, DK);
    zero4_kernel<<<(DK*32+T-1)/T, T>>>((float4*)agg, DK*32);
    edge_agg_kernel<128,true><<<(DE*32+T-1)/T, T>>>(ns, nd, dis2, hp, agg);
    finalize_kernel<128,true><<<(DK*128+T-1)/T, T>>>(hp, agg, dis2, b3, DK);

    // ---- conv4 (128 -> 64), fused with global mean ----
    gemm_kernel<128,64,16><<<(DK+15)/16, T>>>(hp, W4, gm, DK);
    zero4_kernel<<<(DK*16+T-1)/T, T>>>((float4*)agg, DK*16);
    edge_agg_kernel<64,true><<<(DE*16+T-1)/T, T>>>(ns, nd, dis2, gm, agg);
    final_reduce_kernel<<<2048, T>>>(gm, agg, dis2, b4, acc);
    write_out_kernel<<<1,64>>>(acc, out);
}

// round 4
// speedup vs baseline: 1.1487x; 1.1487x over previous
#include <cuda_runtime.h>

typedef unsigned long long u64;

#define DN 50000
#define DE 800000
#define DK 40000
#define NBLK 49   // ceil(DN/1024) for the kept-node compaction

// ---------------- scratch layout (single __device__ blob) ----------------
static constexpr size_t OFF_XW   = 0;                               // DN*128 gemm out
static constexpr size_t OFF_HA   = OFF_XW  + (size_t)DN*128*4;      // DN*128 gather out
static constexpr size_t OFF_HP   = OFF_HA  + (size_t)DN*128*4;      // DK*128 pooled feats
static constexpr size_t OFF_GM   = OFF_HP  + (size_t)DK*128*4;      // DK*64 gemm out
static constexpr size_t OFF_T2   = OFF_GM  + (size_t)DK*64*4;       // DK*64 gather out
static constexpr size_t OFF_DIS1 = OFF_T2  + (size_t)DK*64*4;       // DN
static constexpr size_t OFF_DIS2 = OFF_DIS1 + (size_t)DN*4;         // DK
static constexpr size_t OFF_DEG1 = OFF_DIS2 + (size_t)DK*4;         // DN
static constexpr size_t OFF_DEG2 = OFF_DEG1 + (size_t)DN*4;         // DK
static constexpr size_t OFF_RP1  = OFF_DEG2 + (size_t)DK*4;         // DN+1
static constexpr size_t OFF_CUR1 = OFF_RP1  + (size_t)(DN+1)*4;     // DN
static constexpr size_t OFF_RP2  = OFF_CUR1 + (size_t)DN*4;         // DK+1
static constexpr size_t OFF_CUR2 = OFF_RP2  + (size_t)(DK+1)*4;     // DK
static constexpr size_t OFF_CSR1 = OFF_CUR2 + (size_t)DK*4;         // DE
static constexpr size_t OFF_CSR2 = OFF_CSR1 + (size_t)DE*4;         // DE
static constexpr size_t OFF_NS   = OFF_CSR2 + (size_t)DE*4;         // DE
static constexpr size_t OFF_ND   = OFF_NS   + (size_t)DE*4;         // DE
static constexpr size_t OFF_SCORE= OFF_ND   + (size_t)DE*4;         // DN
static constexpr size_t OFF_KEY  = OFF_SCORE+ (size_t)DN*4;         // DN u64
static constexpr size_t OFF_NEW  = OFF_KEY  + (size_t)DN*8;         // DN
static constexpr size_t OFF_BINS = OFF_NEW  + (size_t)DN*4;
static constexpr size_t OFF_BSUM = OFF_BINS + 256*4;
static constexpr size_t OFF_BOFF = OFF_BSUM + 64*4;
static constexpr size_t OFF_PFX  = OFF_BOFF + 64*4;
static constexpr size_t OFF_REM  = OFF_PFX  + 8;
static constexpr size_t OFF_WN   = OFF_REM  + 4;
static constexpr size_t OFF_ACC  = OFF_WN   + 4;
static constexpr size_t TOTAL_BYTES = OFF_ACC + 64*4;

__device__ __align__(256) unsigned char g_scratch[TOTAL_BYTES];

// ---------------- init: reset all per-replay state in one launch ------------
__global__ void init_kernel(int* deg1, int* deg2, int* bins, float* acc,
                            int* rem, u64* pfx){
    int i = blockIdx.x*blockDim.x + threadIdx.x;
    if (i < DN)  deg1[i] = 0;
    if (i < DK)  deg2[i] = 0;
    if (i < 256) bins[i] = 0;
    if (i < 64)  acc[i]  = 0.f;
    if (i == 0){ *rem = DK; *pfx = 0ull; }
}

// ---------------- register-tiled GEMM: Y[M,KOUT] = X[M,KIN] @ W[KIN,KOUT] ---
template<int KIN, int KOUT, int ROWS>
__global__ void gemm_rt(const float* __restrict__ X, const float* __restrict__ W,
                        float* __restrict__ Y, int M){
    extern __shared__ float sm[];
    float* sW = sm;                 // KIN*KOUT
    float* sX = sm + KIN*KOUT;      // ROWS*KIN
    const int tid = threadIdx.x;
    constexpr int CG = KOUT/4;
    constexpr int RG = ROWS/4;
    for (int i = tid; i < KIN*KOUT/4; i += blockDim.x)
        ((float4*)sW)[i] = ((const float4*)W)[i];
    const int row0 = blockIdx.x * ROWS;
    for (int i = tid; i < ROWS*KIN/4; i += blockDim.x){
        int r  = i / (KIN/4);
        int gr = row0 + r;
        ((float4*)sX)[i] = (gr < M) ? ((const float4*)X)[(size_t)gr*(KIN/4) + (i % (KIN/4))]
                                    : make_float4(0.f,0.f,0.f,0.f);
    }
    __syncthreads();
    const float4* w4 = (const float4*)sW;
    for (int it = tid; it < RG*CG; it += blockDim.x){
        int rg = it / CG, cg = it % CG;
        int r0 = rg*4;
        float4 a0 = make_float4(0,0,0,0), a1 = a0, a2 = a0, a3 = a0;
        #pragma unroll 8
        for (int k = 0; k < KIN; k++){
            float4 w = w4[k*CG + cg];
            float x0 = sX[(r0+0)*KIN + k];
            float x1 = sX[(r0+1)*KIN + k];
            float x2 = sX[(r0+2)*KIN + k];
            float x3 = sX[(r0+3)*KIN + k];
            a0.x += x0*w.x; a0.y += x0*w.y; a0.z += x0*w.z; a0.w += x0*w.w;
            a1.x += x1*w.x; a1.y += x1*w.y; a1.z += x1*w.z; a1.w += x1*w.w;
            a2.x += x2*w.x; a2.y += x2*w.y; a2.z += x2*w.z; a2.w += x2*w.w;
            a3.x += x3*w.x; a3.y += x3*w.y; a3.z += x3*w.z; a3.w += x3*w.w;
        }
        float4* yp = (float4*)Y;
        int gr = row0 + r0;
        if (gr+0 < M) yp[(size_t)(gr+0)*CG + cg] = a0;
        if (gr+1 < M) yp[(size_t)(gr+1)*CG + cg] = a1;
        if (gr+2 < M) yp[(size_t)(gr+2)*CG + cg] = a2;
        if (gr+3 < M) yp[(size_t)(gr+3)*CG + cg] = a3;
    }
}

// ---------------- degree histogram ----------------
__global__ void deg_kernel(const int* __restrict__ dst, int* __restrict__ deg){
    int e = blockIdx.x*blockDim.x + threadIdx.x;
    if (e < DE) atomicAdd(&deg[dst[e]], 1);
}

// ---------------- single-block scan: rowptr/cursor/dis from deg -------------
__global__ void scan_dis_kernel(const int* __restrict__ deg, int* __restrict__ rowptr,
                                int* __restrict__ cur, float* __restrict__ dis, int M){
    __shared__ int sh[1024];
    const int tid = threadIdx.x;
    const int C = (M + 1023) >> 10;
    const int base = tid * C;
    int s = 0;
    for (int c = 0; c < C; c++){ int i = base + c; if (i < M) s += deg[i]; }
    sh[tid] = s;
    __syncthreads();
    for (int off = 1; off < 1024; off <<= 1){
        int v = (tid >= off) ? sh[tid - off] : 0;
        __syncthreads();
        sh[tid] += v;
        __syncthreads();
    }
    int run = sh[tid] - s;   // exclusive prefix
    for (int c = 0; c < C; c++){
        int i = base + c;
        if (i < M){
            int dg = deg[i];
            rowptr[i] = run; cur[i] = run;
            dis[i] = rsqrtf(1.0f + (float)dg);
            run += dg;
        }
    }
    if (tid == 1023) rowptr[M] = sh[1023];
}

// ---------------- CSR scatter ----------------
__global__ void scatter1_kernel(const int* __restrict__ src, const int* __restrict__ dst,
                                int* __restrict__ cur, int* __restrict__ csr){
    int e = blockIdx.x*blockDim.x + threadIdx.x;
    if (e >= DE) return;
    int pos = atomicAdd(&cur[dst[e]], 1);
    csr[pos] = src[e];
}

__global__ void scatter2_kernel(const int* __restrict__ ns, const int* __restrict__ nd,
                                int* __restrict__ cur, int* __restrict__ csr){
    int e = blockIdx.x*blockDim.x + threadIdx.x;
    if (e >= DE) return;
    int a = ns[e];
    if (a < 0) return;
    int pos = atomicAdd(&cur[nd[e]], 1);
    csr[pos] = a;
}

// ---------------- CSR gather + fused GCN epilogue ----------------
// DIM=128: one warp per node, float4 per lane.
template<bool RELU>
__global__ void gather128_kernel(const int* __restrict__ rowptr, const int* __restrict__ csr,
                                 const float* __restrict__ dis, const float* __restrict__ Hin,
                                 const float* __restrict__ bias, float* __restrict__ Hout, int M){
    int w = (blockIdx.x*blockDim.x + threadIdx.x) >> 5;
    int lane = threadIdx.x & 31;
    if (w >= M) return;
    int beg = rowptr[w], end = rowptr[w+1];
    float dn = dis[w];
    float4 h = ((const float4*)Hin)[(size_t)w*32 + lane];
    float s2 = dn*dn;
    float4 acc = make_float4(h.x*s2, h.y*s2, h.z*s2, h.w*s2);
    for (int j = beg; j < end; j++){
        int s = csr[j];
        float c = dis[s] * dn;
        float4 v = ((const float4*)Hin)[(size_t)s*32 + lane];
        acc.x += c*v.x; acc.y += c*v.y; acc.z += c*v.z; acc.w += c*v.w;
    }
    float4 b = ((const float4*)bias)[lane];
    acc.x += b.x; acc.y += b.y; acc.z += b.z; acc.w += b.w;
    if (RELU){
        acc.x = fmaxf(acc.x, 0.f); acc.y = fmaxf(acc.y, 0.f);
        acc.z = fmaxf(acc.z, 0.f); acc.w = fmaxf(acc.w, 0.f);
    }
    ((float4*)Hout)[(size_t)w*32 + lane] = acc;
}

// DIM=64: one warp per node, float2 per lane.
template<bool RELU>
__global__ void gather64_kernel(const int* __restrict__ rowptr, const int* __restrict__ csr,
                                const float* __restrict__ dis, const float* __restrict__ Hin,
                                const float* __restrict__ bias, float* __restrict__ Hout, int M){
    int w = (blockIdx.x*blockDim.x + threadIdx.x) >> 5;
    int lane = threadIdx.x & 31;
    if (w >= M) return;
    int beg = rowptr[w], end = rowptr[w+1];
    float dn = dis[w];
    float2 h = ((const float2*)Hin)[(size_t)w*32 + lane];
    float s2 = dn*dn;
    float2 acc = make_float2(h.x*s2, h.y*s2);
    for (int j = beg; j < end; j++){
        int s = csr[j];
        float c = dis[s] * dn;
        float2 v = ((const float2*)Hin)[(size_t)s*32 + lane];
        acc.x += c*v.x; acc.y += c*v.y;
    }
    float2 b = ((const float2*)bias)[lane];
    acc.x += b.x; acc.y += b.y;
    if (RELU){ acc.x = fmaxf(acc.x, 0.f); acc.y = fmaxf(acc.y, 0.f); }
    ((float2*)Hout)[(size_t)w*32 + lane] = acc;
}

// conv4 gather fused with the global mean accumulation (bias added at writeout)
__global__ void gather64_reduce_kernel(const int* __restrict__ rowptr, const int* __restrict__ csr,
                                       const float* __restrict__ dis, const float* __restrict__ Hin,
                                       float* __restrict__ accOut){
    __shared__ float sh[64];
    const int lane = threadIdx.x & 31;
    const int wloc = threadIdx.x >> 5;
    const int wpb  = blockDim.x >> 5;
    if (threadIdx.x < 64) sh[threadIdx.x] = 0.f;
    __syncthreads();
    int w = blockIdx.x*wpb + wloc;
    int tw = gridDim.x*wpb;
    float2 sum = make_float2(0.f, 0.f);
    for (int n = w; n < DK; n += tw){
        int beg = rowptr[n], end = rowptr[n+1];
        float dn = dis[n];
        float2 h = ((const float2*)Hin)[(size_t)n*32 + lane];
        float s2 = dn*dn;
        float2 a = make_float2(h.x*s2, h.y*s2);
        for (int j = beg; j < end; j++){
            int s = csr[j];
            float c = dis[s] * dn;
            float2 v = ((const float2*)Hin)[(size_t)s*32 + lane];
            a.x += c*v.x; a.y += c*v.y;
        }
        sum.x += a.x; sum.y += a.y;
    }
    atomicAdd(&sh[2*lane],   sum.x);
    atomicAdd(&sh[2*lane+1], sum.y);
    __syncthreads();
    if (threadIdx.x < 64) atomicAdd(&accOut[threadIdx.x], sh[threadIdx.x]);
}

__global__ void write_out_kernel(const float* __restrict__ acc, const float* __restrict__ b4,
                                 float* __restrict__ out){
    if (threadIdx.x < 64)
        out[threadIdx.x] = acc[threadIdx.x] * (1.0f/(float)DK) + b4[threadIdx.x];
}

// ---------------- pooling: score, exact top-K radix select ----------------
__global__ void wnorm_kernel(const float* __restrict__ w, float* wn){
    float v = w[threadIdx.x]; v *= v;
    #pragma unroll
    for (int o = 16; o; o >>= 1) v += __shfl_xor_sync(0xffffffffu, v, o);
    __shared__ float sh[4];
    if ((threadIdx.x & 31) == 0) sh[threadIdx.x >> 5] = v;
    __syncthreads();
    if (threadIdx.x == 0) *wn = sqrtf(sh[0]+sh[1]+sh[2]+sh[3]);
}

__global__ void score_kernel(const float* __restrict__ H, const float* __restrict__ w,
                             const float* __restrict__ wn,
                             float* __restrict__ score, u64* __restrict__ key){
    int t = blockIdx.x*blockDim.x + threadIdx.x;
    int n = t >> 5, lane = t & 31;
    if (n >= DN) return;
    float4 a = ((const float4*)H)[(size_t)n*32 + lane];
    float4 b = ((const float4*)w)[lane];
    float s = a.x*b.x + a.y*b.y + a.z*b.z + a.w*b.w;
    #pragma unroll
    for (int o = 16; o; o >>= 1) s += __shfl_xor_sync(0xffffffffu, s, o);
    if (lane == 0){
        s = tanhf(s / *wn);
        score[n] = s;
        unsigned ub = __float_as_uint(s);
        ub = (ub & 0x80000000u) ? ~ub : (ub | 0x80000000u);   // order-preserving map
        key[n] = ((u64)ub << 32) | (u64)(0xffffffffu - (unsigned)n);  // distinct keys
    }
}

__global__ void hist_kernel(const u64* __restrict__ key, int* __restrict__ bins,
                            const u64* __restrict__ pfxp, int shift){
    __shared__ int sb[256];
    if (threadIdx.x < 256) sb[threadIdx.x] = 0;
    __syncthreads();
    u64 pfx = *pfxp;
    for (int n = blockIdx.x*blockDim.x + threadIdx.x; n < DN; n += gridDim.x*blockDim.x){
        u64 k = key[n];
        bool ok = (shift == 56) || ((k >> (shift+8)) == (pfx >> (shift+8)));
        if (ok) atomicAdd(&sb[(int)((k >> shift) & 0xFF)], 1);
    }
    __syncthreads();
    if (threadIdx.x < 256 && sb[threadIdx.x]) atomicAdd(&bins[threadIdx.x], sb[threadIdx.x]);
}

__global__ void select_kernel(int* bins, u64* pfxp, int* remp, int shift){
    int rem = *remp;
    u64 pfx = *pfxp;
    for (int b = 255; b >= 0; b--){
        int c = bins[b];
        if (rem <= c){ pfx |= ((u64)b) << shift; break; }
        rem -= c;
    }
    *remp = rem;
    *pfxp = pfx;
    for (int i = 0; i < 256; i++) bins[i] = 0;
}

// ---------------- compaction: new_idx for kept nodes ----------------
__global__ void count_kept_kernel(const u64* __restrict__ key, const u64* __restrict__ pfxp,
                                  int* __restrict__ bsum){
    __shared__ int sh[256];
    u64 pfx = *pfxp;
    int tid = threadIdx.x;
    int base = blockIdx.x*1024 + tid*4;
    int c = 0;
    #pragma unroll
    for (int j = 0; j < 4; j++){
        int n = base + j;
        if (n < DN && key[n] >= pfx) c++;
    }
    sh[tid] = c;
    __syncthreads();
    for (int s = 128; s; s >>= 1){
        if (tid < s) sh[tid] += sh[tid + s];
        __syncthreads();
    }
    if (tid == 0) bsum[blockIdx.x] = sh[0];
}

__global__ void scan_kernel(const int* bsum, int* boff){
    int acc = 0;
    for (int i = 0; i < NBLK; i++){ boff[i] = acc; acc += bsum[i]; }
}

__global__ void newidx_kernel(const u64* __restrict__ key, const u64* __restrict__ pfxp,
                              const int* __restrict__ boff, int* __restrict__ newidx){
    __shared__ int sh[256];
    u64 pfx = *pfxp;
    int tid = threadIdx.x;
    int base = blockIdx.x*1024 + tid*4;
    int kept[4]; int cnt = 0;
    #pragma unroll
    for (int j = 0; j < 4; j++){
        int n = base + j;
        kept[j] = (n < DN && key[n] >= pfx) ? 1 : 0;
        cnt += kept[j];
    }
    sh[tid] = cnt;
    __syncthreads();
    for (int s = 1; s < 256; s <<= 1){
        int v = (tid >= s) ? sh[tid - s] : 0;
        __syncthreads();
        sh[tid] += v;
        __syncthreads();
    }
    int off = boff[blockIdx.x] + sh[tid] - cnt;   // exclusive prefix
    #pragma unroll
    for (int j = 0; j < 4; j++){
        int n = base + j;
        if (n < DN) newidx[n] = kept[j] ? off++ : -1;
    }
}

__global__ void build_hp_kernel(const float* __restrict__ H, const int* __restrict__ newidx,
                                const float* __restrict__ score, float* __restrict__ HP){
    int i = blockIdx.x*blockDim.x + threadIdx.x;
    if (i >= DN*32) return;
    int n = i >> 5;
    int ni = newidx[n];
    if (ni < 0) return;
    float s = score[n];
    float4 v = ((const float4*)H)[i];
    v.x *= s; v.y *= s; v.z *= s; v.w *= s;
    ((float4*)HP)[(size_t)ni*32 + (i & 31)] = v;
}

__global__ void remap_kernel(const int* __restrict__ src, const int* __restrict__ dst,
                             const int* __restrict__ newidx,
                             int* __restrict__ ns, int* __restrict__ nd, int* __restrict__ deg){
    int e = blockIdx.x*blockDim.x + threadIdx.x;
    if (e >= DE) return;
    int a = newidx[src[e]];
    int b = newidx[dst[e]];
    if (a >= 0 && b >= 0){
        ns[e] = a; nd[e] = b;
        atomicAdd(&deg[b], 1);
    } else { ns[e] = -1; nd[e] = -1; }
}

// ---------------- launch ----------------
extern "C" void kernel_launch(void* const* d_in, const int* in_sizes, int n_in,
                              void* d_out, int out_size){
    const float* x   = (const float*)d_in[0];
    const int*   ei  = (const int*)  d_in[1];
    const int*   src = ei;
    const int*   dst = ei + DE;
    const float* W1  = (const float*)d_in[3];
    const float* b1  = (const float*)d_in[4];
    const float* pw  = (const float*)d_in[5];
    const float* W2  = (const float*)d_in[6];
    const float* b2  = (const float*)d_in[7];
    const float* W3  = (const float*)d_in[8];
    const float* b3  = (const float*)d_in[9];
    const float* W4  = (const float*)d_in[10];
    const float* b4  = (const float*)d_in[11];
    float* out = (float*)d_out;

    void* basep = nullptr;
    cudaGetSymbolAddress(&basep, g_scratch);
    unsigned char* B = (unsigned char*)basep;
    float* xw    = (float*)(B + OFF_XW);
    float* ha    = (float*)(B + OFF_HA);
    float* hp    = (float*)(B + OFF_HP);
    float* gm    = (float*)(B + OFF_GM);
    float* t2    = (float*)(B + OFF_T2);
    float* dis1  = (float*)(B + OFF_DIS1);
    float* dis2  = (float*)(B + OFF_DIS2);
    int*   deg1  = (int*)  (B + OFF_DEG1);
    int*   deg2  = (int*)  (B + OFF_DEG2);
    int*   rp1   = (int*)  (B + OFF_RP1);
    int*   cur1  = (int*)  (B + OFF_CUR1);
    int*   rp2   = (int*)  (B + OFF_RP2);
    int*   cur2  = (int*)  (B + OFF_CUR2);
    int*   csr1  = (int*)  (B + OFF_CSR1);
    int*   csr2  = (int*)  (B + OFF_CSR2);
    int*   ns    = (int*)  (B + OFF_NS);
    int*   nd    = (int*)  (B + OFF_ND);
    float* score = (float*)(B + OFF_SCORE);
    u64*   key   = (u64*)  (B + OFF_KEY);
    int*   nidx  = (int*)  (B + OFF_NEW);
    int*   bins  = (int*)  (B + OFF_BINS);
    int*   bsum  = (int*)  (B + OFF_BSUM);
    int*   boff  = (int*)  (B + OFF_BOFF);
    u64*   pfx   = (u64*)  (B + OFF_PFX);
    int*   rem   = (int*)  (B + OFF_REM);
    float* wn    = (float*)(B + OFF_WN);
    float* acc   = (float*)(B + OFF_ACC);

    const int T = 256;
    const int SMEM_G1 = (64*128 + 64*64)*4;    // 49152 (default limit, ok)
    const int SMEM_G2 = (128*64 + 64*128)*4;   // 65536 (needs opt-in)
    cudaFuncSetAttribute(gemm_rt<128,64,64>, cudaFuncAttributeMaxDynamicSharedMemorySize, SMEM_G2);

    // init counters / accumulators (graph replays must fully reset state)
    init_kernel<<<(DN+T-1)/T, T>>>(deg1, deg2, bins, acc, rem, pfx);

    // ---- conv1 on full graph (CSR gather) ----
    gemm_rt<64,128,64><<<(DN+63)/64, T, SMEM_G1>>>(x, W1, xw, DN);
    deg_kernel<<<(DE+T-1)/T, T>>>(dst, deg1);
    scan_dis_kernel<<<1, 1024>>>(deg1, rp1, cur1, dis1, DN);
    scatter1_kernel<<<(DE+T-1)/T, T>>>(src, dst, cur1, csr1);
    gather128_kernel<true><<<(DN*32+T-1)/T, T>>>(rp1, csr1, dis1, xw, b1, ha, DN);

    // ---- TopK pooling (exact, radix select over 64-bit keys) ----
    wnorm_kernel<<<1,128>>>(pw, wn);
    score_kernel<<<(DN*32+T-1)/T, T>>>(ha, pw, wn, score, key);
    for (int shift = 56; shift >= 0; shift -= 8){
        hist_kernel<<<128, T>>>(key, bins, pfx, shift);
        select_kernel<<<1,1>>>(bins, pfx, rem, shift);
    }
    count_kept_kernel<<<NBLK, T>>>(key, pfx, bsum);
    scan_kernel<<<1,1>>>(bsum, boff);
    newidx_kernel<<<NBLK, T>>>(key, pfx, boff, nidx);
    build_hp_kernel<<<(DN*32+T-1)/T, T>>>(ha, nidx, score, hp);
    remap_kernel<<<(DE+T-1)/T, T>>>(src, dst, nidx, ns, nd, deg2);
    scan_dis_kernel<<<1, 1024>>>(deg2, rp2, cur2, dis2, DK);
    scatter2_kernel<<<(DE+T-1)/T, T>>>(ns, nd, cur2, csr2);

    // ---- conv2 (128 -> 64) + relu ----
    gemm_rt<128,64,64><<<(DK+63)/64, T, SMEM_G2>>>(hp, W2, gm, DK);
    gather64_kernel<true><<<(DK*32+T-1)/T, T>>>(rp2, csr2, dis2, gm, b2, t2, DK);

    // ---- conv3 (64 -> 128) + relu ----
    gemm_rt<64,128,64><<<(DK+63)/64, T, SMEM_G1>>>(t2, W3, xw, DK);
    gather128_kernel<true><<<(DK*32+T-1)/T, T>>>(rp2, csr2, dis2, xw, b3, ha, DK);

    // ---- conv4 (128 -> 64), fused with global mean ----
    gemm_rt<128,64,64><<<(DK+63)/64, T, SMEM_G2>>>(ha, W4, gm, DK);
    gather64_reduce_kernel<<<296, T>>>(rp2, csr2, dis2, gm, acc);
    write_out_kernel<<<1,64>>>(acc, b4, out);
}

// round 5
// speedup vs baseline: 1.7057x; 1.4849x over previous
#include <cuda_runtime.h>

typedef unsigned long long u64;

#define DN 50000
#define DE 800000
#define DK 40000
#define NBLK 49   // ceil(DN/1024) for the kept-node compaction

// ---------------- scratch layout (single __device__ blob) ----------------
static constexpr size_t OFF_XW   = 0;                               // DN*128 gemm out
static constexpr size_t OFF_HA   = OFF_XW  + (size_t)DN*128*4;      // DN*128 gather out
static constexpr size_t OFF_HP   = OFF_HA  + (size_t)DN*128*4;      // DK*128 pooled feats
static constexpr size_t OFF_GM   = OFF_HP  + (size_t)DK*128*4;      // DK*64 gemm out
static constexpr size_t OFF_T2   = OFF_GM  + (size_t)DK*64*4;       // DK*64 gather out
static constexpr size_t OFF_DIS1 = OFF_T2  + (size_t)DK*64*4;       // DN
static constexpr size_t OFF_DIS2 = OFF_DIS1 + (size_t)DN*4;         // DK
static constexpr size_t OFF_DEG1 = OFF_DIS2 + (size_t)DK*4;         // DN
static constexpr size_t OFF_DEG2 = OFF_DEG1 + (size_t)DN*4;         // DK
static constexpr size_t OFF_RP1  = OFF_DEG2 + (size_t)DK*4;         // DN+1
static constexpr size_t OFF_CUR1 = OFF_RP1  + (size_t)(DN+1)*4;     // DN
static constexpr size_t OFF_RP2  = OFF_CUR1 + (size_t)DN*4;         // DK+1
static constexpr size_t OFF_CUR2 = OFF_RP2  + (size_t)(DK+1)*4;     // DK
static constexpr size_t OFF_CSR1 = OFF_CUR2 + (size_t)DK*4;         // DE
static constexpr size_t OFF_CSR2 = OFF_CSR1 + (size_t)DE*4;         // DE
static constexpr size_t OFF_NS   = OFF_CSR2 + (size_t)DE*4;         // DE
static constexpr size_t OFF_ND   = OFF_NS   + (size_t)DE*4;         // DE
static constexpr size_t OFF_SCORE= OFF_ND   + (size_t)DE*4;         // DN
static constexpr size_t OFF_KEY  = OFF_SCORE+ (size_t)DN*4;         // DN u64
static constexpr size_t OFF_NEW  = OFF_KEY  + (size_t)DN*8;         // DN
static constexpr size_t OFF_BINS = OFF_NEW  + (size_t)DN*4;
static constexpr size_t OFF_BSUM = OFF_BINS + 256*4;                // 64 (reused: scan partials & compaction)
static constexpr size_t OFF_BOFF = OFF_BSUM + 64*4;
static constexpr size_t OFF_PFX  = OFF_BOFF + 64*4;
static constexpr size_t OFF_REM  = OFF_PFX  + 8;
static constexpr size_t OFF_WN   = OFF_REM  + 4;
static constexpr size_t OFF_ACC  = OFF_WN   + 4;
static constexpr size_t TOTAL_BYTES = OFF_ACC + 64*4;

__device__ __align__(256) unsigned char g_scratch[TOTAL_BYTES];

// ---------------- init: reset all per-replay state in one launch ------------
__global__ void init_kernel(int* deg1, int* deg2, int* bins, float* acc,
                            int* rem, u64* pfx){
    int i = blockIdx.x*blockDim.x + threadIdx.x;
    if (i < DN)  deg1[i] = 0;
    if (i < DK)  deg2[i] = 0;
    if (i < 256) bins[i] = 0;
    if (i < 64)  acc[i]  = 0.f;
    if (i == 0){ *rem = DK; *pfx = 0ull; }
}

// ---------------- register-tiled GEMM: Y[M,KOUT] = X[M,KIN] @ W[KIN,KOUT] ---
template<int KIN, int KOUT, int ROWS>
__global__ void gemm_rt(const float* __restrict__ X, const float* __restrict__ W,
                        float* __restrict__ Y, int M){
    extern __shared__ float sm[];
    float* sW = sm;                 // KIN*KOUT
    float* sX = sm + KIN*KOUT;      // ROWS*KIN
    const int tid = threadIdx.x;
    constexpr int CG = KOUT/4;
    constexpr int RG = ROWS/4;
    for (int i = tid; i < KIN*KOUT/4; i += blockDim.x)
        ((float4*)sW)[i] = ((const float4*)W)[i];
    const int row0 = blockIdx.x * ROWS;
    for (int i = tid; i < ROWS*KIN/4; i += blockDim.x){
        int r  = i / (KIN/4);
        int gr = row0 + r;
        ((float4*)sX)[i] = (gr < M) ? ((const float4*)X)[(size_t)gr*(KIN/4) + (i % (KIN/4))]
                                    : make_float4(0.f,0.f,0.f,0.f);
    }
    __syncthreads();
    const float4* w4 = (const float4*)sW;
    for (int it = tid; it < RG*CG; it += blockDim.x){
        int rg = it / CG, cg = it % CG;
        int r0 = rg*4;
        float4 a0 = make_float4(0,0,0,0), a1 = a0, a2 = a0, a3 = a0;
        #pragma unroll 8
        for (int k = 0; k < KIN; k++){
            float4 w = w4[k*CG + cg];
            float x0 = sX[(r0+0)*KIN + k];
            float x1 = sX[(r0+1)*KIN + k];
            float x2 = sX[(r0+2)*KIN + k];
            float x3 = sX[(r0+3)*KIN + k];
            a0.x += x0*w.x; a0.y += x0*w.y; a0.z += x0*w.z; a0.w += x0*w.w;
            a1.x += x1*w.x; a1.y += x1*w.y; a1.z += x1*w.z; a1.w += x1*w.w;
            a2.x += x2*w.x; a2.y += x2*w.y; a2.z += x2*w.z; a2.w += x2*w.w;
            a3.x += x3*w.x; a3.y += x3*w.y; a3.z += x3*w.z; a3.w += x3*w.w;
        }
        float4* yp = (float4*)Y;
        int gr = row0 + r0;
        if (gr+0 < M) yp[(size_t)(gr+0)*CG + cg] = a0;
        if (gr+1 < M) yp[(size_t)(gr+1)*CG + cg] = a1;
        if (gr+2 < M) yp[(size_t)(gr+2)*CG + cg] = a2;
        if (gr+3 < M) yp[(size_t)(gr+3)*CG + cg] = a3;
    }
}

// ---------------- degree histogram ----------------
__global__ void deg_kernel(const int* __restrict__ dst, int* __restrict__ deg){
    int e = blockIdx.x*blockDim.x + threadIdx.x;
    if (e < DE) atomicAdd(&deg[dst[e]], 1);
}

// ---------------- 3-phase device-wide scan (replaces 101us single-block) ----
// Phase A: per-1024-chunk sums
__global__ void blocksum_kernel(const int* __restrict__ deg, int* __restrict__ bsums, int M){
    __shared__ int sh[256];
    int tid = threadIdx.x;
    int base = blockIdx.x * 1024;
    int s = 0;
    #pragma unroll
    for (int j = 0; j < 4; j++){
        int i = base + tid + j*256;
        if (i < M) s += deg[i];
    }
    sh[tid] = s;
    __syncthreads();
    for (int o = 128; o; o >>= 1){
        if (tid < o) sh[tid] += sh[tid + o];
        __syncthreads();
    }
    if (tid == 0) bsums[blockIdx.x] = sh[0];
}

// Phase B: exclusive scan of <=64 partials (trivial)
__global__ void bscan_kernel(int* __restrict__ bsums, int nb){
    if (threadIdx.x == 0){
        int acc = 0;
        for (int i = 0; i < nb; i++){ int v = bsums[i]; bsums[i] = acc; acc += v; }
    }
}

// Phase C: per-block inclusive scan + chunk offset; writes rowptr/cur/dis
__global__ void scanwrite_kernel(const int* __restrict__ deg, const int* __restrict__ bsums,
                                 int* __restrict__ rowptr, int* __restrict__ cur,
                                 float* __restrict__ dis, int M){
    __shared__ int sh[1024];
    int tid = threadIdx.x;
    int i = blockIdx.x*1024 + tid;
    int v = (i < M) ? deg[i] : 0;
    sh[tid] = v;
    __syncthreads();
    #pragma unroll
    for (int o = 1; o < 1024; o <<= 1){
        int t = (tid >= o) ? sh[tid - o] : 0;
        __syncthreads();
        sh[tid] += t;
        __syncthreads();
    }
    if (i < M){
        int excl = bsums[blockIdx.x] + sh[tid] - v;
        rowptr[i] = excl;
        cur[i]    = excl;
        dis[i]    = rsqrtf(1.0f + (float)v);
        if (i == M-1) rowptr[M] = excl + v;
    }
}

// ---------------- CSR scatter ----------------
__global__ void scatter1_kernel(const int* __restrict__ src, const int* __restrict__ dst,
                                int* __restrict__ cur, int* __restrict__ csr){
    int e = blockIdx.x*blockDim.x + threadIdx.x;
    if (e >= DE) return;
    int pos = atomicAdd(&cur[dst[e]], 1);
    csr[pos] = src[e];
}

__global__ void scatter2_kernel(const int* __restrict__ ns, const int* __restrict__ nd,
                                int* __restrict__ cur, int* __restrict__ csr){
    int e = blockIdx.x*blockDim.x + threadIdx.x;
    if (e >= DE) return;
    int a = ns[e];
    if (a < 0) return;
    int pos = atomicAdd(&cur[nd[e]], 1);
    csr[pos] = a;
}

// ---------------- CSR gather + fused GCN epilogue ----------------
// DIM=128: one warp per node, float4 per lane.
template<bool RELU>
__global__ void gather128_kernel(const int* __restrict__ rowptr, const int* __restrict__ csr,
                                 const float* __restrict__ dis, const float* __restrict__ Hin,
                                 const float* __restrict__ bias, float* __restrict__ Hout, int M){
    int w = (blockIdx.x*blockDim.x + threadIdx.x) >> 5;
    int lane = threadIdx.x & 31;
    if (w >= M) return;
    int beg = rowptr[w], end = rowptr[w+1];
    float dn = dis[w];
    float4 h = ((const float4*)Hin)[(size_t)w*32 + lane];
    float s2 = dn*dn;
    float4 acc = make_float4(h.x*s2, h.y*s2, h.z*s2, h.w*s2);
    for (int j = beg; j < end; j++){
        int s = csr[j];
        float c = dis[s] * dn;
        float4 v = ((const float4*)Hin)[(size_t)s*32 + lane];
        acc.x += c*v.x; acc.y += c*v.y; acc.z += c*v.z; acc.w += c*v.w;
    }
    float4 b = ((const float4*)bias)[lane];
    acc.x += b.x; acc.y += b.y; acc.z += b.z; acc.w += b.w;
    if (RELU){
        acc.x = fmaxf(acc.x, 0.f); acc.y = fmaxf(acc.y, 0.f);
        acc.z = fmaxf(acc.z, 0.f); acc.w = fmaxf(acc.w, 0.f);
    }
    ((float4*)Hout)[(size_t)w*32 + lane] = acc;
}

// DIM=64: one warp per node, float2 per lane.
template<bool RELU>
__global__ void gather64_kernel(const int* __restrict__ rowptr, const int* __restrict__ csr,
                                const float* __restrict__ dis, const float* __restrict__ Hin,
                                const float* __restrict__ bias, float* __restrict__ Hout, int M){
    int w = (blockIdx.x*blockDim.x + threadIdx.x) >> 5;
    int lane = threadIdx.x & 31;
    if (w >= M) return;
    int beg = rowptr[w], end = rowptr[w+1];
    float dn = dis[w];
    float2 h = ((const float2*)Hin)[(size_t)w*32 + lane];
    float s2 = dn*dn;
    float2 acc = make_float2(h.x*s2, h.y*s2);
    for (int j = beg; j < end; j++){
        int s = csr[j];
        float c = dis[s] * dn;
        float2 v = ((const float2*)Hin)[(size_t)s*32 + lane];
        acc.x += c*v.x; acc.y += c*v.y;
    }
    float2 b = ((const float2*)bias)[lane];
    acc.x += b.x; acc.y += b.y;
    if (RELU){ acc.x = fmaxf(acc.x, 0.f); acc.y = fmaxf(acc.y, 0.f); }
    ((float2*)Hout)[(size_t)w*32 + lane] = acc;
}

// conv4 gather fused with the global mean accumulation (bias added at writeout)
__global__ void gather64_reduce_kernel(const int* __restrict__ rowptr, const int* __restrict__ csr,
                                       const float* __restrict__ dis, const float* __restrict__ Hin,
                                       float* __restrict__ accOut){
    __shared__ float sh[64];
    const int lane = threadIdx.x & 31;
    const int wloc = threadIdx.x >> 5;
    const int wpb  = blockDim.x >> 5;
    if (threadIdx.x < 64) sh[threadIdx.x] = 0.f;
    __syncthreads();
    int w = blockIdx.x*wpb + wloc;
    int tw = gridDim.x*wpb;
    float2 sum = make_float2(0.f, 0.f);
    for (int n = w; n < DK; n += tw){
        int beg = rowptr[n], end = rowptr[n+1];
        float dn = dis[n];
        float2 h = ((const float2*)Hin)[(size_t)n*32 + lane];
        float s2 = dn*dn;
        float2 a = make_float2(h.x*s2, h.y*s2);
        for (int j = beg; j < end; j++){
            int s = csr[j];
            float c = dis[s] * dn;
            float2 v = ((const float2*)Hin)[(size_t)s*32 + lane];
            a.x += c*v.x; a.y += c*v.y;
        }
        sum.x += a.x; sum.y += a.y;
    }
    atomicAdd(&sh[2*lane],   sum.x);
    atomicAdd(&sh[2*lane+1], sum.y);
    __syncthreads();
    if (threadIdx.x < 64) atomicAdd(&accOut[threadIdx.x], sh[threadIdx.x]);
}

__global__ void write_out_kernel(const float* __restrict__ acc, const float* __restrict__ b4,
                                 float* __restrict__ out){
    if (threadIdx.x < 64)
        out[threadIdx.x] = acc[threadIdx.x] * (1.0f/(float)DK) + b4[threadIdx.x];
}

// ---------------- pooling: score, exact top-K radix select ----------------
__global__ void wnorm_kernel(const float* __restrict__ w, float* wn){
    float v = w[threadIdx.x]; v *= v;
    #pragma unroll
    for (int o = 16; o; o >>= 1) v += __shfl_xor_sync(0xffffffffu, v, o);
    __shared__ float sh[4];
    if ((threadIdx.x & 31) == 0) sh[threadIdx.x >> 5] = v;
    __syncthreads();
    if (threadIdx.x == 0) *wn = sqrtf(sh[0]+sh[1]+sh[2]+sh[3]);
}

__global__ void score_kernel(const float* __restrict__ H, const float* __restrict__ w,
                             const float* __restrict__ wn,
                             float* __restrict__ score, u64* __restrict__ key){
    int t = blockIdx.x*blockDim.x + threadIdx.x;
    int n = t >> 5, lane = t & 31;
    if (n >= DN) return;
    float4 a = ((const float4*)H)[(size_t)n*32 + lane];
    float4 b = ((const float4*)w)[lane];
    float s = a.x*b.x + a.y*b.y + a.z*b.z + a.w*b.w;
    #pragma unroll
    for (int o = 16; o; o >>= 1) s += __shfl_xor_sync(0xffffffffu, s, o);
    if (lane == 0){
        s = tanhf(s / *wn);
        score[n] = s;
        unsigned ub = __float_as_uint(s);
        ub = (ub & 0x80000000u) ? ~ub : (ub | 0x80000000u);   // order-preserving map
        key[n] = ((u64)ub << 32) | (u64)(0xffffffffu - (unsigned)n);  // distinct keys
    }
}

__global__ void hist_kernel(const u64* __restrict__ key, int* __restrict__ bins,
                            const u64* __restrict__ pfxp, int shift){
    __shared__ int sb[256];
    if (threadIdx.x < 256) sb[threadIdx.x] = 0;
    __syncthreads();
    u64 pfx = *pfxp;
    for (int n = blockIdx.x*blockDim.x + threadIdx.x; n < DN; n += gridDim.x*blockDim.x){
        u64 k = key[n];
        bool ok = (shift == 56) || ((k >> (shift+8)) == (pfx >> (shift+8)));
        if (ok) atomicAdd(&sb[(int)((k >> shift) & 0xFF)], 1);
    }
    __syncthreads();
    if (threadIdx.x < 256 && sb[threadIdx.x]) atomicAdd(&bins[threadIdx.x], sb[threadIdx.x]);
}

__global__ void select_kernel(int* bins, u64* pfxp, int* remp, int shift){
    int rem = *remp;
    u64 pfx = *pfxp;
    for (int b = 255; b >= 0; b--){
        int c = bins[b];
        if (rem <= c){ pfx |= ((u64)b) << shift; break; }
        rem -= c;
    }
    *remp = rem;
    *pfxp = pfx;
    for (int i = 0; i < 256; i++) bins[i] = 0;
}

// ---------------- compaction: new_idx for kept nodes ----------------
__global__ void count_kept_kernel(const u64* __restrict__ key, const u64* __restrict__ pfxp,
                                  int* __restrict__ bsum){
    __shared__ int sh[256];
    u64 pfx = *pfxp;
    int tid = threadIdx.x;
    int base = blockIdx.x*1024 + tid*4;
    int c = 0;
    #pragma unroll
    for (int j = 0; j < 4; j++){
        int n = base + j;
        if (n < DN && key[n] >= pfx) c++;
    }
    sh[tid] = c;
    __syncthreads();
    for (int s = 128; s; s >>= 1){
        if (tid < s) sh[tid] += sh[tid + s];
        __syncthreads();
    }
    if (tid == 0) bsum[blockIdx.x] = sh[0];
}

__global__ void scan_kernel(const int* bsum, int* boff){
    int acc = 0;
    for (int i = 0; i < NBLK; i++){ boff[i] = acc; acc += bsum[i]; }
}

__global__ void newidx_kernel(const u64* __restrict__ key, const u64* __restrict__ pfxp,
                              const int* __restrict__ boff, int* __restrict__ newidx){
    __shared__ int sh[256];
    u64 pfx = *pfxp;
    int tid = threadIdx.x;
    int base = blockIdx.x*1024 + tid*4;
    int kept[4]; int cnt = 0;
    #pragma unroll
    for (int j = 0; j < 4; j++){
        int n = base + j;
        kept[j] = (n < DN && key[n] >= pfx) ? 1 : 0;
        cnt += kept[j];
    }
    sh[tid] = cnt;
    __syncthreads();
    for (int s = 1; s < 256; s <<= 1){
        int v = (tid >= s) ? sh[tid - s] : 0;
        __syncthreads();
        sh[tid] += v;
        __syncthreads();
    }
    int off = boff[blockIdx.x] + sh[tid] - cnt;   // exclusive prefix
    #pragma unroll
    for (int j = 0; j < 4; j++){
        int n = base + j;
        if (n < DN) newidx[n] = kept[j] ? off++ : -1;
    }
}

__global__ void build_hp_kernel(const float* __restrict__ H, const int* __restrict__ newidx,
                                const float* __restrict__ score, float* __restrict__ HP){
    int i = blockIdx.x*blockDim.x + threadIdx.x;
    if (i >= DN*32) return;
    int n = i >> 5;
    int ni = newidx[n];
    if (ni < 0) return;
    float s = score[n];
    float4 v = ((const float4*)H)[i];
    v.x *= s; v.y *= s; v.z *= s; v.w *= s;
    ((float4*)HP)[(size_t)ni*32 + (i & 31)] = v;
}

__global__ void remap_kernel(const int* __restrict__ src, const int* __restrict__ dst,
                             const int* __restrict__ newidx,
                             int* __restrict__ ns, int* __restrict__ nd, int* __restrict__ deg){
    int e = blockIdx.x*blockDim.x + threadIdx.x;
    if (e >= DE) return;
    int a = newidx[src[e]];
    int b = newidx[dst[e]];
    if (a >= 0 && b >= 0){
        ns[e] = a; nd[e] = b;
        atomicAdd(&deg[b], 1);
    } else { ns[e] = -1; nd[e] = -1; }
}

// ---------------- launch ----------------
extern "C" void kernel_launch(void* const* d_in, const int* in_sizes, int n_in,
                              void* d_out, int out_size){
    const float* x   = (const float*)d_in[0];
    const int*   ei  = (const int*)  d_in[1];
    const int*   src = ei;
    const int*   dst = ei + DE;
    const float* W1  = (const float*)d_in[3];
    const float* b1  = (const float*)d_in[4];
    const float* pw  = (const float*)d_in[5];
    const float* W2  = (const float*)d_in[6];
    const float* b2  = (const float*)d_in[7];
    const float* W3  = (const float*)d_in[8];
    const float* b3  = (const float*)d_in[9];
    const float* W4  = (const float*)d_in[10];
    const float* b4  = (const float*)d_in[11];
    float* out = (float*)d_out;

    void* basep = nullptr;
    cudaGetSymbolAddress(&basep, g_scratch);
    unsigned char* B = (unsigned char*)basep;
    float* xw    = (float*)(B + OFF_XW);
    float* ha    = (float*)(B + OFF_HA);
    float* hp    = (float*)(B + OFF_HP);
    float* gm    = (float*)(B + OFF_GM);
    float* t2    = (float*)(B + OFF_T2);
    float* dis1  = (float*)(B + OFF_DIS1);
    float* dis2  = (float*)(B + OFF_DIS2);
    int*   deg1  = (int*)  (B + OFF_DEG1);
    int*   deg2  = (int*)  (B + OFF_DEG2);
    int*   rp1   = (int*)  (B + OFF_RP1);
    int*   cur1  = (int*)  (B + OFF_CUR1);
    int*   rp2   = (int*)  (B + OFF_RP2);
    int*   cur2  = (int*)  (B + OFF_CUR2);
    int*   csr1  = (int*)  (B + OFF_CSR1);
    int*   csr2  = (int*)  (B + OFF_CSR2);
    int*   ns    = (int*)  (B + OFF_NS);
    int*   nd    = (int*)  (B + OFF_ND);
    float* score = (float*)(B + OFF_SCORE);
    u64*   key   = (u64*)  (B + OFF_KEY);
    int*   nidx  = (int*)  (B + OFF_NEW);
    int*   bins  = (int*)  (B + OFF_BINS);
    int*   bsum  = (int*)  (B + OFF_BSUM);
    int*   boff  = (int*)  (B + OFF_BOFF);
    u64*   pfx   = (u64*)  (B + OFF_PFX);
    int*   rem   = (int*)  (B + OFF_REM);
    float* wn    = (float*)(B + OFF_WN);
    float* acc   = (float*)(B + OFF_ACC);

    const int T = 256;
    const int NB1 = (DN + 1023)/1024;   // 49
    const int NB2 = (DK + 1023)/1024;   // 40
    const int SMEM_G1 = (64*128 + 64*64)*4;    // 49152
    const int SMEM_G2 = (128*64 + 64*128)*4;   // 65536 (needs opt-in)
    cudaFuncSetAttribute(gemm_rt<128,64,64>, cudaFuncAttributeMaxDynamicSharedMemorySize, SMEM_G2);

    // init counters / accumulators (graph replays must fully reset state)
    init_kernel<<<(DN+T-1)/T, T>>>(deg1, deg2, bins, acc, rem, pfx);

    // ---- conv1 on full graph (CSR gather) ----
    gemm_rt<64,128,64><<<(DN+63)/64, T, SMEM_G1>>>(x, W1, xw, DN);
    deg_kernel<<<(DE+T-1)/T, T>>>(dst, deg1);
    blocksum_kernel<<<NB1, 256>>>(deg1, bsum, DN);
    bscan_kernel<<<1, 32>>>(bsum, NB1);
    scanwrite_kernel<<<NB1, 1024>>>(deg1, bsum, rp1, cur1, dis1, DN);
    scatter1_kernel<<<(DE+T-1)/T, T>>>(src, dst, cur1, csr1);
    gather128_kernel<true><<<(DN*32+T-1)/T, T>>>(rp1, csr1, dis1, xw, b1, ha, DN);

    // ---- TopK pooling (exact, radix select over 64-bit keys) ----
    wnorm_kernel<<<1,128>>>(pw, wn);
    score_kernel<<<(DN*32+T-1)/T, T>>>(ha, pw, wn, score, key);
    for (int shift = 56; shift >= 0; shift -= 8){
        hist_kernel<<<128, T>>>(key, bins, pfx, shift);
        select_kernel<<<1,1>>>(bins, pfx, rem, shift);
    }
    count_kept_kernel<<<NBLK, T>>>(key, pfx, bsum);
    scan_kernel<<<1,1>>>(bsum, boff);
    newidx_kernel<<<NBLK, T>>>(key, pfx, boff, nidx);
    build_hp_kernel<<<(DN*32+T-1)/T, T>>>(ha, nidx, score, hp);
    remap_kernel<<<(DE+T-1)/T, T>>>(src, dst, nidx, ns, nd, deg2);
    blocksum_kernel<<<NB2, 256>>>(deg2, bsum, DK);
    bscan_kernel<<<1, 32>>>(bsum, NB2);
    scanwrite_kernel<<<NB2, 1024>>>(deg2, bsum, rp2, cur2, dis2, DK);
    scatter2_kernel<<<(DE+T-1)/T, T>>>(ns, nd, cur2, csr2);

    // ---- conv2 (128 -> 64) + relu ----
    gemm_rt<128,64,64><<<(DK+63)/64, T, SMEM_G2>>>(hp, W2, gm, DK);
    gather64_kernel<true><<<(DK*32+T-1)/T, T>>>(rp2, csr2, dis2, gm, b2, t2, DK);

    // ---- conv3 (64 -> 128) + relu ----
    gemm_rt<64,128,64><<<(DK+63)/64, T, SMEM_G1>>>(t2, W3, xw, DK);
    gather128_kernel<true><<<(DK*32+T-1)/T, T>>>(rp2, csr2, dis2, xw, b3, ha, DK);

    // ---- conv4 (128 -> 64), fused with global mean ----
    gemm_rt<128,64,64><<<(DK+63)/64, T, SMEM_G2>>>(ha, W4, gm, DK);
    gather64_reduce_kernel<<<296, T>>>(rp2, csr2, dis2, gm, acc);
    write_out_kernel<<<1,64>>>(acc, b4, out);
}